// round 6
// baseline (speedup 1.0000x reference)
#include <cuda_runtime.h>
#include <cuda_bf16.h>
#include <cstdint>

// Problem dims
#define DD 2048
#define HH 1408
#define EE 8
#define TT 4096
#define CAP 4096

#define BK 32
#define NS1 (DD / BK)   // 64
#define NS2 (HH / BK)   // 44
#define AST 36                    // SMEM row stride in words (144B): conflict-free frags
#define OFF_B_W (128 * AST)       // B region word offset within a stage
#define STAGE_W (384 * AST)       // A 128 rows + B 256 rows
#define STAGE_B (STAGE_W * 4)     // 55296 bytes
#define SMEM_DYN (512 + 3 * STAGE_B)  // 166400

// ---- global scratch (no allocs allowed) ----
__device__ int   g_count[EE];
__device__ int   g_tokens[EE * CAP];
__device__ float g_w[EE * CAP];
__device__ int   g_tidx[TT * 2];
__device__ float g_tw[TT * 2];
__device__ float g_G[(size_t)EE * CAP * HH];   // SwiGLU activations, fp32 (tf32-rounded)

// ---------------------------------------------------------------------------
__device__ __forceinline__ uint32_t smem_u32(const void* p) {
    uint32_t a;
    asm("{ .reg .u64 t; cvta.to.shared.u64 t, %1; cvt.u32.u64 %0, t; }" : "=r"(a) : "l"(p));
    return a;
}
#define CP16(dst, src) \
    asm volatile("cp.async.cg.shared.global [%0], [%1], 16;" :: "r"(dst), "l"(src) : "memory")
#define CP_COMMIT() asm volatile("cp.async.commit_group;" ::: "memory")
#define CP_WAIT1()  asm volatile("cp.async.wait_group 1;" ::: "memory")

__device__ __forceinline__ void mma_tf32(float* c, const uint32_t* a,
                                         uint32_t b0, uint32_t b1) {
    asm volatile(
        "mma.sync.aligned.m16n8k8.row.col.f32.tf32.tf32.f32 "
        "{%0,%1,%2,%3},{%4,%5,%6,%7},{%8,%9},{%0,%1,%2,%3};"
        : "+f"(c[0]), "+f"(c[1]), "+f"(c[2]), "+f"(c[3])
        : "r"(a[0]), "r"(a[1]), "r"(a[2]), "r"(a[3]), "r"(b0), "r"(b1));
}
__device__ __forceinline__ float f2tf_rna(float v) {
    uint32_t r;
    asm("cvt.rna.tf32.f32 %0, %1;" : "=r"(r) : "f"(v));
    return __uint_as_float(r);
}
__device__ __forceinline__ float silu_f(float v) { return v / (1.0f + expf(-v)); }

// ---------------------------------------------------------------------------
__global__ void k_init() {
    int i = blockIdx.x * blockDim.x + threadIdx.x;
    if (i < EE * CAP) { g_tokens[i] = 0; g_w[i] = 0.0f; }
    if (i < EE) g_count[i] = 0;
}

__global__ void k_gate(const float* __restrict__ x,
                       const float* __restrict__ Wg,
                       float* __restrict__ out) {
    int warp = threadIdx.x >> 5, lane = threadIdx.x & 31;
    int t = blockIdx.x * 8 + warp;
    float a[EE];
#pragma unroll
    for (int e = 0; e < EE; e++) a[e] = 0.0f;
    const float* xr = x + (size_t)t * DD;
    float* orow = out + (size_t)t * DD;
    for (int k = lane; k < DD; k += 32) {
        float xv = xr[k];
        orow[k] = xv;
#pragma unroll
        for (int e = 0; e < EE; e++) a[e] += xv * Wg[e * DD + k];
    }
#pragma unroll
    for (int off = 16; off; off >>= 1) {
#pragma unroll
        for (int e = 0; e < EE; e++) a[e] += __shfl_xor_sync(0xffffffffu, a[e], off);
    }
    if (lane == 0) {
        float m = a[0];
#pragma unroll
        for (int e = 1; e < EE; e++) m = fmaxf(m, a[e]);
        float s = 0.0f;
#pragma unroll
        for (int e = 0; e < EE; e++) s += expf(a[e] - m);
        int i1 = 0;
#pragma unroll
        for (int e = 1; e < EE; e++) if (a[e] > a[i1]) i1 = e;
        int i2 = (i1 == 0) ? 1 : 0;
#pragma unroll
        for (int e = 0; e < EE; e++) if (e != i1 && a[e] > a[i2]) i2 = e;
        g_tidx[t * 2 + 0] = i1; g_tw[t * 2 + 0] = expf(a[i1] - m) / s;
        g_tidx[t * 2 + 1] = i2; g_tw[t * 2 + 1] = expf(a[i2] - m) / s;
    }
}

__global__ void k_route() {
    int t = blockIdx.x * blockDim.x + threadIdx.x;
    if (t >= TT) return;
#pragma unroll
    for (int k = 0; k < 2; k++) {
        int e = g_tidx[t * 2 + k];
        int pos = atomicAdd(&g_count[e], 1);
        g_tokens[e * CAP + pos] = t;
        g_w[e * CAP + pos] = g_tw[t * 2 + k];
    }
}

// ---------------------------------------------------------------------------
// gemm1: block 128M x 256N (128 H-cols; B rows interleave W1/W3 in 32-row
// groups so silu pairing is warp-local). 8 warps, warp tile 64x64, BK=32,
// 3-stage cp.async, raw-fp32-as-tf32 HMMA.
// ---------------------------------------------------------------------------
__global__ void __launch_bounds__(256, 1) k_gemm1(const float* __restrict__ x,
                                                  const float* __restrict__ W1,
                                                  const float* __restrict__ W3) {
    int e = blockIdx.z;
    int cnt = g_count[e];
    int m0 = blockIdx.x * 128;
    if (m0 >= cnt) return;
    int n0h = blockIdx.y * 128;   // H-column offset (this block does 128 H cols)

    extern __shared__ __align__(16) char smem[];
    int* srow = (int*)smem;
    float* stages = (float*)(smem + 512);
    uint32_t sb = smem_u32(smem);
    int tid = threadIdx.x, w = tid >> 5, lane = tid & 31, gr = lane >> 2, tg = lane & 3;
    int wm = w >> 2, wn = w & 3;

    if (tid < 128) srow[tid] = g_tokens[e * CAP + m0 + tid] * DD;
    __syncthreads();

    const float* w1b = W1 + ((size_t)e * HH + n0h) * DD;
    const float* w3b = W3 + ((size_t)e * HH + n0h) * DD;

    auto issue = [&](int s) {
        if (s < NS1) {
            int k0 = s * BK;
            uint32_t bs = sb + 512 + (s % 3) * STAGE_B;
#pragma unroll
            for (int i = 0; i < 4; i++) {          // A: 128 rows x 8 chunks
                int u = tid + i * 256, row = u >> 3, c4 = u & 7;
                CP16(bs + (row * AST + c4 * 4) * 4, x + srow[row] + k0 + c4 * 4);
            }
#pragma unroll
            for (int i = 0; i < 8; i++) {          // B: 256 rows x 8 chunks
                int u = tid + i * 256, row = u >> 3, c4 = u & 7;
                int colh = (row >> 6) * 32 + (row & 31);
                const float* src = ((row & 32) ? w3b : w1b) + (size_t)colh * DD;
                CP16(bs + ((OFF_B_W + row * AST) + c4 * 4) * 4, src + k0 + c4 * 4);
            }
        }
        CP_COMMIT();
    };

    float acc[4][8][4];
#pragma unroll
    for (int mi = 0; mi < 4; mi++)
#pragma unroll
        for (int ni = 0; ni < 8; ni++)
#pragma unroll
            for (int q = 0; q < 4; q++) acc[mi][ni][q] = 0.0f;

    issue(0);
    issue(1);
    for (int s = 0; s < NS1; s++) {
        CP_WAIT1();
        __syncthreads();
        issue(s + 2);
        const float* st = stages + (s % 3) * STAGE_W;
        const float* sB = st + OFF_B_W;
#pragma unroll
        for (int ks = 0; ks < 32; ks += 8) {
            uint32_t a[4][4];
#pragma unroll
            for (int mi = 0; mi < 4; mi++) {
                int r0 = wm * 64 + mi * 16 + gr;
                a[mi][0] = *(const uint32_t*)&st[r0 * AST + ks + tg];
                a[mi][1] = *(const uint32_t*)&st[(r0 + 8) * AST + ks + tg];
                a[mi][2] = *(const uint32_t*)&st[r0 * AST + ks + tg + 4];
                a[mi][3] = *(const uint32_t*)&st[(r0 + 8) * AST + ks + tg + 4];
            }
#pragma unroll
            for (int ni = 0; ni < 8; ni++) {
                int n = wn * 64 + ni * 8 + gr;
                uint32_t b0 = *(const uint32_t*)&sB[n * AST + ks + tg];
                uint32_t b1 = *(const uint32_t*)&sB[n * AST + ks + tg + 4];
#pragma unroll
                for (int mi = 0; mi < 4; mi++)
                    mma_tf32(acc[mi][ni], a[mi], b0, b1);
            }
        }
    }

    // epilogue: warp-local silu pairing (ni = W1 block, ni+4 = W3 block),
    // pre-round G to tf32 (RNA) so gemm2's in-MMA truncation is exact.
#pragma unroll
    for (int mi = 0; mi < 4; mi++) {
        int r = m0 + wm * 64 + mi * 16 + gr;
        float* gp = g_G + ((size_t)e * CAP + r) * HH + n0h + wn * 32;
#pragma unroll
        for (int ni = 0; ni < 4; ni++) {
            int c = ni * 8 + tg * 2;
            float2 v0, v1;
            v0.x = f2tf_rna(silu_f(acc[mi][ni][0]) * acc[mi][ni + 4][0]);
            v0.y = f2tf_rna(silu_f(acc[mi][ni][1]) * acc[mi][ni + 4][1]);
            v1.x = f2tf_rna(silu_f(acc[mi][ni][2]) * acc[mi][ni + 4][2]);
            v1.y = f2tf_rna(silu_f(acc[mi][ni][3]) * acc[mi][ni + 4][3]);
            *(float2*)(gp + c) = v0;
            *(float2*)(gp + (size_t)8 * HH + c) = v1;
        }
    }
}

// ---------------------------------------------------------------------------
// gemm2: block 128M x 256N (d-cols), K over H; 8 warps, warp tile 64x64.
// Weighted atomic scatter-add into out (pre-initialized to residual x).
// ---------------------------------------------------------------------------
__global__ void __launch_bounds__(256, 1) k_gemm2(const float* __restrict__ W2,
                                                  float* __restrict__ out) {
    int e = blockIdx.z;
    int cnt = g_count[e];
    int m0 = blockIdx.x * 128;
    if (m0 >= cnt) return;
    int n0 = blockIdx.y * 256;

    extern __shared__ __align__(16) char smem[];
    float* stages = (float*)(smem + 512);
    uint32_t sb = smem_u32(smem);
    int tid = threadIdx.x, w = tid >> 5, lane = tid & 31, gr = lane >> 2, tg = lane & 3;
    int wm = w >> 2, wn = w & 3;

    const float* ab  = g_G + ((size_t)e * CAP + m0) * HH;
    const float* w2b = W2 + ((size_t)e * DD + n0) * HH;

    auto issue = [&](int s) {
        if (s < NS2) {
            int k0 = s * BK;
            uint32_t bs = sb + 512 + (s % 3) * STAGE_B;
#pragma unroll
            for (int i = 0; i < 4; i++) {
                int u = tid + i * 256, row = u >> 3, c4 = u & 7;
                CP16(bs + (row * AST + c4 * 4) * 4, ab + (size_t)row * HH + k0 + c4 * 4);
            }
#pragma unroll
            for (int i = 0; i < 8; i++) {
                int u = tid + i * 256, row = u >> 3, c4 = u & 7;
                CP16(bs + ((OFF_B_W + row * AST) + c4 * 4) * 4,
                     w2b + (size_t)row * HH + k0 + c4 * 4);
            }
        }
        CP_COMMIT();
    };

    float acc[4][8][4];
#pragma unroll
    for (int mi = 0; mi < 4; mi++)
#pragma unroll
        for (int ni = 0; ni < 8; ni++)
#pragma unroll
            for (int q = 0; q < 4; q++) acc[mi][ni][q] = 0.0f;

    issue(0);
    issue(1);
    for (int s = 0; s < NS2; s++) {
        CP_WAIT1();
        __syncthreads();
        issue(s + 2);
        const float* st = stages + (s % 3) * STAGE_W;
        const float* sB = st + OFF_B_W;
#pragma unroll
        for (int ks = 0; ks < 32; ks += 8) {
            uint32_t a[4][4];
#pragma unroll
            for (int mi = 0; mi < 4; mi++) {
                int r0 = wm * 64 + mi * 16 + gr;
                a[mi][0] = *(const uint32_t*)&st[r0 * AST + ks + tg];
                a[mi][1] = *(const uint32_t*)&st[(r0 + 8) * AST + ks + tg];
                a[mi][2] = *(const uint32_t*)&st[r0 * AST + ks + tg + 4];
                a[mi][3] = *(const uint32_t*)&st[(r0 + 8) * AST + ks + tg + 4];
            }
#pragma unroll
            for (int ni = 0; ni < 8; ni++) {
                int n = wn * 64 + ni * 8 + gr;
                uint32_t b0 = *(const uint32_t*)&sB[n * AST + ks + tg];
                uint32_t b1 = *(const uint32_t*)&sB[n * AST + ks + tg + 4];
#pragma unroll
                for (int mi = 0; mi < 4; mi++)
                    mma_tf32(acc[mi][ni], a[mi], b0, b1);
            }
        }
    }

    // epilogue: weighted scatter-add
#pragma unroll
    for (int mi = 0; mi < 4; mi++) {
        int rl = m0 + wm * 64 + mi * 16 + gr;
        int t0 = g_tokens[e * CAP + rl];
        float w0 = g_w[e * CAP + rl];
        int t1 = g_tokens[e * CAP + rl + 8];
        float w1 = g_w[e * CAP + rl + 8];
        float* o0 = out + (size_t)t0 * DD + n0 + wn * 64;
        float* o1 = out + (size_t)t1 * DD + n0 + wn * 64;
#pragma unroll
        for (int ni = 0; ni < 8; ni++) {
            int c = ni * 8 + tg * 2;
            atomicAdd(o0 + c,     w0 * acc[mi][ni][0]);
            atomicAdd(o0 + c + 1, w0 * acc[mi][ni][1]);
            atomicAdd(o1 + c,     w1 * acc[mi][ni][2]);
            atomicAdd(o1 + c + 1, w1 * acc[mi][ni][3]);
        }
    }
}

// ---------------------------------------------------------------------------
extern "C" void kernel_launch(void* const* d_in, const int* in_sizes, int n_in,
                              void* d_out, int out_size) {
    (void)in_sizes; (void)n_in; (void)out_size;
    const float* x  = (const float*)d_in[0];
    const float* Wg = (const float*)d_in[1];
    const float* W1 = (const float*)d_in[2];
    const float* W3 = (const float*)d_in[3];
    const float* W2 = (const float*)d_in[4];
    float* out = (float*)d_out;

    cudaFuncSetAttribute(k_gemm1, cudaFuncAttributeMaxDynamicSharedMemorySize, SMEM_DYN);
    cudaFuncSetAttribute(k_gemm2, cudaFuncAttributeMaxDynamicSharedMemorySize, SMEM_DYN);

    k_init<<<(EE * CAP + 255) / 256, 256>>>();
    k_gate<<<TT / 8, 256>>>(x, Wg, out);
    k_route<<<TT / 256, 256>>>();
    dim3 g1(CAP / 128, HH / 128, EE);
    k_gemm1<<<g1, 256, SMEM_DYN>>>(x, W1, W3);
    dim3 g2(CAP / 128, DD / 256, EE);
    k_gemm2<<<g2, 256, SMEM_DYN>>>(W2, out);
}

// round 7
// speedup vs baseline: 1.0892x; 1.0892x over previous
#include <cuda_runtime.h>
#include <cuda_bf16.h>
#include <cstdint>

// Problem dims
#define DD 2048
#define HH 1408
#define EE 8
#define TT 4096
#define CAP 4096

#define BK 32
#define NS1 (DD / BK)   // 64
#define NS2 (HH / BK)   // 44
#define AST 36                    // SMEM row stride in words (144B): conflict-free frags
#define OFF_B_W (128 * AST)       // B region word offset within a stage
#define STAGE_W (256 * AST)       // A 128 rows + B 128 rows
#define STAGE_B (STAGE_W * 4)     // 36864 bytes
#define SMEM_DYN (512 + 2 * STAGE_B)  // 74240 -> 2 CTAs/SM

// ---- global scratch (no allocs allowed) ----
__device__ int   g_count[EE];
__device__ int   g_tokens[EE * CAP];
__device__ float g_w[EE * CAP];
__device__ int   g_tidx[TT * 2];
__device__ float g_tw[TT * 2];
__device__ float g_G[(size_t)EE * CAP * HH];   // SwiGLU activations (tf32-rounded fp32)

// ---------------------------------------------------------------------------
__device__ __forceinline__ uint32_t smem_u32(const void* p) {
    uint32_t a;
    asm("{ .reg .u64 t; cvta.to.shared.u64 t, %1; cvt.u32.u64 %0, t; }" : "=r"(a) : "l"(p));
    return a;
}
#define CP16(dst, src) \
    asm volatile("cp.async.cg.shared.global [%0], [%1], 16;" :: "r"(dst), "l"(src) : "memory")
#define CP_COMMIT() asm volatile("cp.async.commit_group;" ::: "memory")
#define CP_WAIT0()  asm volatile("cp.async.wait_group 0;" ::: "memory")

__device__ __forceinline__ void mma_tf32(float* c, const uint32_t* a,
                                         uint32_t b0, uint32_t b1) {
    asm volatile(
        "mma.sync.aligned.m16n8k8.row.col.f32.tf32.tf32.f32 "
        "{%0,%1,%2,%3},{%4,%5,%6,%7},{%8,%9},{%0,%1,%2,%3};"
        : "+f"(c[0]), "+f"(c[1]), "+f"(c[2]), "+f"(c[3])
        : "r"(a[0]), "r"(a[1]), "r"(a[2]), "r"(a[3]), "r"(b0), "r"(b1));
}
__device__ __forceinline__ float f2tf_rna(float v) {
    uint32_t r;
    asm("cvt.rna.tf32.f32 %0, %1;" : "=r"(r) : "f"(v));
    return __uint_as_float(r);
}
__device__ __forceinline__ float silu_f(float v) { return v / (1.0f + expf(-v)); }

// ---------------------------------------------------------------------------
__global__ void k_init() {
    int i = blockIdx.x * blockDim.x + threadIdx.x;
    if (i < EE * CAP) { g_tokens[i] = 0; g_w[i] = 0.0f; }
    if (i < EE) g_count[i] = 0;
}

// gating: one warp per token, float4-vectorized; also writes out = x (residual).
__global__ void k_gate(const float* __restrict__ x,
                       const float* __restrict__ Wg,
                       float* __restrict__ out) {
    int warp = threadIdx.x >> 5, lane = threadIdx.x & 31;
    int t = blockIdx.x * 8 + warp;
    float a[EE];
#pragma unroll
    for (int e = 0; e < EE; e++) a[e] = 0.0f;
    const float4* xr = (const float4*)(x + (size_t)t * DD);
    const float4* wg = (const float4*)Wg;
    float4* orow = (float4*)(out + (size_t)t * DD);
#pragma unroll 4
    for (int k = lane; k < DD / 4; k += 32) {
        float4 xv = xr[k];
        orow[k] = xv;
#pragma unroll
        for (int e = 0; e < EE; e++) {
            float4 wv = wg[e * (DD / 4) + k];
            a[e] += xv.x * wv.x + xv.y * wv.y + xv.z * wv.z + xv.w * wv.w;
        }
    }
#pragma unroll
    for (int off = 16; off; off >>= 1) {
#pragma unroll
        for (int e = 0; e < EE; e++) a[e] += __shfl_xor_sync(0xffffffffu, a[e], off);
    }
    if (lane == 0) {
        float m = a[0];
#pragma unroll
        for (int e = 1; e < EE; e++) m = fmaxf(m, a[e]);
        float s = 0.0f;
#pragma unroll
        for (int e = 0; e < EE; e++) s += expf(a[e] - m);
        int i1 = 0;
#pragma unroll
        for (int e = 1; e < EE; e++) if (a[e] > a[i1]) i1 = e;
        int i2 = (i1 == 0) ? 1 : 0;
#pragma unroll
        for (int e = 0; e < EE; e++) if (e != i1 && a[e] > a[i2]) i2 = e;
        g_tidx[t * 2 + 0] = i1; g_tw[t * 2 + 0] = expf(a[i1] - m) / s;
        g_tidx[t * 2 + 1] = i2; g_tw[t * 2 + 1] = expf(a[i2] - m) / s;
    }
}

__global__ void k_route() {
    int t = blockIdx.x * blockDim.x + threadIdx.x;
    if (t >= TT) return;
#pragma unroll
    for (int k = 0; k < 2; k++) {
        int e = g_tidx[t * 2 + k];
        int pos = atomicAdd(&g_count[e], 1);
        g_tokens[e * CAP + pos] = t;
        g_w[e * CAP + pos] = g_tw[t * 2 + k];
    }
}

// ---------------------------------------------------------------------------
// gemm1: block 128M x 128N (64 W1 cols | 64 W3 cols), BK=32, 4 warps,
// warp tile 32x128. 2-stage cp.async pipeline -> 2 CTAs/SM. Raw-fp32-as-tf32.
// ---------------------------------------------------------------------------
__global__ void __launch_bounds__(128, 2) k_gemm1(const float* __restrict__ x,
                                                  const float* __restrict__ W1,
                                                  const float* __restrict__ W3) {
    int e = blockIdx.z;
    int cnt = g_count[e];
    int m0 = blockIdx.x * 128;
    if (m0 >= cnt) return;
    int n0 = blockIdx.y * 64;

    extern __shared__ __align__(16) char smem[];
    int* srow = (int*)smem;
    float* stages = (float*)(smem + 512);
    uint32_t sb = smem_u32(smem);
    int tid = threadIdx.x, w = tid >> 5, lane = tid & 31, gr = lane >> 2, tg = lane & 3;

    srow[tid] = g_tokens[e * CAP + m0 + tid] * DD;
    __syncthreads();

    const float* w1b = W1 + ((size_t)e * HH + n0) * DD;
    const float* w3b = W3 + ((size_t)e * HH + n0) * DD;

    auto issue = [&](int s) {
        if (s < NS1) {
            int k0 = s * BK;
            uint32_t bs = sb + 512 + (s & 1) * STAGE_B;
#pragma unroll
            for (int i = 0; i < 8; i++) {
                int u = tid + i * 128, row = u >> 3, c4 = u & 7;
                CP16(bs + (row * AST + c4 * 4) * 4, x + srow[row] + k0 + c4 * 4);
            }
#pragma unroll
            for (int i = 0; i < 8; i++) {
                int u = tid + i * 128, row = u >> 3, c4 = u & 7;
                const float* src = (row < 64) ? (w1b + (size_t)row * DD)
                                              : (w3b + (size_t)(row - 64) * DD);
                CP16(bs + (OFF_B_W + row * AST + c4 * 4) * 4, src + k0 + c4 * 4);
            }
        }
        CP_COMMIT();
    };

    float acc[2][16][4];
#pragma unroll
    for (int mi = 0; mi < 2; mi++)
#pragma unroll
        for (int ni = 0; ni < 16; ni++)
#pragma unroll
            for (int q = 0; q < 4; q++) acc[mi][ni][q] = 0.0f;

    issue(0);
    for (int s = 0; s < NS1; s++) {
        CP_WAIT0();
        __syncthreads();
        issue(s + 1);
        const float* st = stages + (s & 1) * STAGE_W;
        const float* sB = st + OFF_B_W;
#pragma unroll
        for (int ks = 0; ks < 32; ks += 8) {
            uint32_t a[2][4];
#pragma unroll
            for (int mi = 0; mi < 2; mi++) {
                int r0 = w * 32 + mi * 16 + gr;
                a[mi][0] = *(const uint32_t*)&st[r0 * AST + ks + tg];
                a[mi][1] = *(const uint32_t*)&st[(r0 + 8) * AST + ks + tg];
                a[mi][2] = *(const uint32_t*)&st[r0 * AST + ks + tg + 4];
                a[mi][3] = *(const uint32_t*)&st[(r0 + 8) * AST + ks + tg + 4];
            }
#pragma unroll
            for (int ni = 0; ni < 16; ni++) {
                int n = ni * 8 + gr;
                uint32_t b0 = *(const uint32_t*)&sB[n * AST + ks + tg];
                uint32_t b1 = *(const uint32_t*)&sB[n * AST + ks + tg + 4];
                mma_tf32(acc[0][ni], a[0], b0, b1);
                mma_tf32(acc[1][ni], a[1], b0, b1);
            }
        }
    }

    // epilogue: silu pairing warp-local (ni = W1 col block, ni+8 = W3),
    // pre-round G to tf32 RNA so gemm2's in-MMA truncation is exact.
#pragma unroll
    for (int mi = 0; mi < 2; mi++) {
        int r = m0 + w * 32 + mi * 16 + gr;
        float* gp = g_G + ((size_t)e * CAP + r) * HH + n0;
#pragma unroll
        for (int ni = 0; ni < 8; ni++) {
            int c = ni * 8 + tg * 2;
            float2 v0, v1;
            v0.x = f2tf_rna(silu_f(acc[mi][ni][0]) * acc[mi][ni + 8][0]);
            v0.y = f2tf_rna(silu_f(acc[mi][ni][1]) * acc[mi][ni + 8][1]);
            v1.x = f2tf_rna(silu_f(acc[mi][ni][2]) * acc[mi][ni + 8][2]);
            v1.y = f2tf_rna(silu_f(acc[mi][ni][3]) * acc[mi][ni + 8][3]);
            *(float2*)(gp + c) = v0;
            *(float2*)(gp + (size_t)8 * HH + c) = v1;
        }
    }
}

// ---------------------------------------------------------------------------
// gemm2: block 128M x 128N (d-cols), K over H; same pipeline; weighted
// atomic scatter-add into out (pre-initialized to residual x).
// ---------------------------------------------------------------------------
__global__ void __launch_bounds__(128, 2) k_gemm2(const float* __restrict__ W2,
                                                  float* __restrict__ out) {
    int e = blockIdx.z;
    int cnt = g_count[e];
    int m0 = blockIdx.x * 128;
    if (m0 >= cnt) return;
    int n0 = blockIdx.y * 128;

    extern __shared__ __align__(16) char smem[];
    float* stages = (float*)(smem + 512);
    uint32_t sb = smem_u32(smem);
    int tid = threadIdx.x, w = tid >> 5, lane = tid & 31, gr = lane >> 2, tg = lane & 3;

    const float* ab  = g_G + ((size_t)e * CAP + m0) * HH;
    const float* w2b = W2 + ((size_t)e * DD + n0) * HH;

    auto issue = [&](int s) {
        if (s < NS2) {
            int k0 = s * BK;
            uint32_t bs = sb + 512 + (s & 1) * STAGE_B;
#pragma unroll
            for (int i = 0; i < 8; i++) {
                int u = tid + i * 128, row = u >> 3, c4 = u & 7;
                CP16(bs + (row * AST + c4 * 4) * 4, ab + (size_t)row * HH + k0 + c4 * 4);
            }
#pragma unroll
            for (int i = 0; i < 8; i++) {
                int u = tid + i * 128, row = u >> 3, c4 = u & 7;
                CP16(bs + (OFF_B_W + row * AST + c4 * 4) * 4, w2b + (size_t)row * HH + k0 + c4 * 4);
            }
        }
        CP_COMMIT();
    };

    float acc[2][16][4];
#pragma unroll
    for (int mi = 0; mi < 2; mi++)
#pragma unroll
        for (int ni = 0; ni < 16; ni++)
#pragma unroll
            for (int q = 0; q < 4; q++) acc[mi][ni][q] = 0.0f;

    issue(0);
    for (int s = 0; s < NS2; s++) {
        CP_WAIT0();
        __syncthreads();
        issue(s + 1);
        const float* st = stages + (s & 1) * STAGE_W;
        const float* sB = st + OFF_B_W;
#pragma unroll
        for (int ks = 0; ks < 32; ks += 8) {
            uint32_t a[2][4];
#pragma unroll
            for (int mi = 0; mi < 2; mi++) {
                int r0 = w * 32 + mi * 16 + gr;
                a[mi][0] = *(const uint32_t*)&st[r0 * AST + ks + tg];
                a[mi][1] = *(const uint32_t*)&st[(r0 + 8) * AST + ks + tg];
                a[mi][2] = *(const uint32_t*)&st[r0 * AST + ks + tg + 4];
                a[mi][3] = *(const uint32_t*)&st[(r0 + 8) * AST + ks + tg + 4];
            }
#pragma unroll
            for (int ni = 0; ni < 16; ni++) {
                int n = ni * 8 + gr;
                uint32_t b0 = *(const uint32_t*)&sB[n * AST + ks + tg];
                uint32_t b1 = *(const uint32_t*)&sB[n * AST + ks + tg + 4];
                mma_tf32(acc[0][ni], a[0], b0, b1);
                mma_tf32(acc[1][ni], a[1], b0, b1);
            }
        }
    }

    // epilogue: weighted scatter-add
#pragma unroll
    for (int mi = 0; mi < 2; mi++) {
        int rl = m0 + w * 32 + mi * 16 + gr;
        int t0 = g_tokens[e * CAP + rl];
        float w0 = g_w[e * CAP + rl];
        int t1 = g_tokens[e * CAP + rl + 8];
        float w1 = g_w[e * CAP + rl + 8];
        float* o0 = out + (size_t)t0 * DD + n0;
        float* o1 = out + (size_t)t1 * DD + n0;
#pragma unroll
        for (int ni = 0; ni < 16; ni++) {
            int c = ni * 8 + tg * 2;
            atomicAdd(o0 + c,     w0 * acc[mi][ni][0]);
            atomicAdd(o0 + c + 1, w0 * acc[mi][ni][1]);
            atomicAdd(o1 + c,     w1 * acc[mi][ni][2]);
            atomicAdd(o1 + c + 1, w1 * acc[mi][ni][3]);
        }
    }
}

// ---------------------------------------------------------------------------
extern "C" void kernel_launch(void* const* d_in, const int* in_sizes, int n_in,
                              void* d_out, int out_size) {
    (void)in_sizes; (void)n_in; (void)out_size;
    const float* x  = (const float*)d_in[0];
    const float* Wg = (const float*)d_in[1];
    const float* W1 = (const float*)d_in[2];
    const float* W3 = (const float*)d_in[3];
    const float* W2 = (const float*)d_in[4];
    float* out = (float*)d_out;

    cudaFuncSetAttribute(k_gemm1, cudaFuncAttributeMaxDynamicSharedMemorySize, SMEM_DYN);
    cudaFuncSetAttribute(k_gemm2, cudaFuncAttributeMaxDynamicSharedMemorySize, SMEM_DYN);

    k_init<<<(EE * CAP + 255) / 256, 256>>>();
    k_gate<<<TT / 8, 256>>>(x, Wg, out);
    k_route<<<TT / 256, 256>>>();
    dim3 g1(CAP / 128, HH / 64, EE);
    k_gemm1<<<g1, 128, SMEM_DYN>>>(x, W1, W3);
    dim3 g2(CAP / 128, DD / 128, EE);
    k_gemm2<<<g2, 128, SMEM_DYN>>>(W2, out);
}

// round 8
// speedup vs baseline: 1.1046x; 1.0141x over previous
#include <cuda_runtime.h>
#include <cuda_bf16.h>
#include <cstdint>

// Problem dims
#define DD 2048
#define HH 1408
#define EE 8
#define TT 4096
#define CAP 4096

#define BK 32
#define NS1 (DD / BK)   // 64
#define NS2 (HH / BK)   // 44
#define AST 36                    // SMEM row stride in words (144B): conflict-free frags
#define OFF_B_W (128 * AST)       // B region word offset within a stage
#define STAGE_W (256 * AST)       // A 128 rows + B 128 rows
#define STAGE_B (STAGE_W * 4)     // 36864 bytes
#define SMEM_DYN (512 + 2 * STAGE_B)  // 74240 -> 2 CTAs/SM

// ---- global scratch (no allocs allowed) ----
__device__ int   g_count[EE];
__device__ int   g_tokens[EE * CAP];
__device__ float g_w[EE * CAP];
__device__ int   g_tidx[TT * 2];
__device__ float g_tw[TT * 2];
__device__ float g_G[(size_t)EE * CAP * HH];   // SwiGLU activations (tf32-rounded fp32)

// ---------------------------------------------------------------------------
__device__ __forceinline__ uint32_t smem_u32(const void* p) {
    uint32_t a;
    asm("{ .reg .u64 t; cvta.to.shared.u64 t, %1; cvt.u32.u64 %0, t; }" : "=r"(a) : "l"(p));
    return a;
}
#define CP16(dst, src) \
    asm volatile("cp.async.cg.shared.global [%0], [%1], 16;" :: "r"(dst), "l"(src) : "memory")
#define CP_COMMIT() asm volatile("cp.async.commit_group;" ::: "memory")
#define CP_WAIT0()  asm volatile("cp.async.wait_group 0;" ::: "memory")

__device__ __forceinline__ void mma_tf32(float* c, const uint32_t* a,
                                         uint32_t b0, uint32_t b1) {
    asm volatile(
        "mma.sync.aligned.m16n8k8.row.col.f32.tf32.tf32.f32 "
        "{%0,%1,%2,%3},{%4,%5,%6,%7},{%8,%9},{%0,%1,%2,%3};"
        : "+f"(c[0]), "+f"(c[1]), "+f"(c[2]), "+f"(c[3])
        : "r"(a[0]), "r"(a[1]), "r"(a[2]), "r"(a[3]), "r"(b0), "r"(b1));
}
__device__ __forceinline__ float f2tf_rna(float v) {
    uint32_t r;
    asm("cvt.rna.tf32.f32 %0, %1;" : "=r"(r) : "f"(v));
    return __uint_as_float(r);
}
__device__ __forceinline__ float silu_f(float v) { return v / (1.0f + expf(-v)); }

// ---------------------------------------------------------------------------
__global__ void k_init() {
    int i = blockIdx.x * blockDim.x + threadIdx.x;
    if (i < EE * CAP) { g_tokens[i] = 0; g_w[i] = 0.0f; }
    if (i < EE) g_count[i] = 0;
}

// gating: one warp per token, float4-vectorized; also writes out = x (residual).
__global__ void k_gate(const float* __restrict__ x,
                       const float* __restrict__ Wg,
                       float* __restrict__ out) {
    int warp = threadIdx.x >> 5, lane = threadIdx.x & 31;
    int t = blockIdx.x * 8 + warp;
    float a[EE];
#pragma unroll
    for (int e = 0; e < EE; e++) a[e] = 0.0f;
    const float4* xr = (const float4*)(x + (size_t)t * DD);
    const float4* wg = (const float4*)Wg;
    float4* orow = (float4*)(out + (size_t)t * DD);
#pragma unroll 4
    for (int k = lane; k < DD / 4; k += 32) {
        float4 xv = xr[k];
        orow[k] = xv;
#pragma unroll
        for (int e = 0; e < EE; e++) {
            float4 wv = wg[e * (DD / 4) + k];
            a[e] += xv.x * wv.x + xv.y * wv.y + xv.z * wv.z + xv.w * wv.w;
        }
    }
#pragma unroll
    for (int off = 16; off; off >>= 1) {
#pragma unroll
        for (int e = 0; e < EE; e++) a[e] += __shfl_xor_sync(0xffffffffu, a[e], off);
    }
    if (lane == 0) {
        float m = a[0];
#pragma unroll
        for (int e = 1; e < EE; e++) m = fmaxf(m, a[e]);
        float s = 0.0f;
#pragma unroll
        for (int e = 0; e < EE; e++) s += expf(a[e] - m);
        int i1 = 0;
#pragma unroll
        for (int e = 1; e < EE; e++) if (a[e] > a[i1]) i1 = e;
        int i2 = (i1 == 0) ? 1 : 0;
#pragma unroll
        for (int e = 0; e < EE; e++) if (e != i1 && a[e] > a[i2]) i2 = e;
        g_tidx[t * 2 + 0] = i1; g_tw[t * 2 + 0] = expf(a[i1] - m) / s;
        g_tidx[t * 2 + 1] = i2; g_tw[t * 2 + 1] = expf(a[i2] - m) / s;
    }
}

__global__ void k_route() {
    int t = blockIdx.x * blockDim.x + threadIdx.x;
    if (t >= TT) return;
#pragma unroll
    for (int k = 0; k < 2; k++) {
        int e = g_tidx[t * 2 + k];
        int pos = atomicAdd(&g_count[e], 1);
        g_tokens[e * CAP + pos] = t;
        g_w[e * CAP + pos] = g_tw[t * 2 + k];
    }
}

// ---------------------------------------------------------------------------
// gemm1: block 128M x 128N, 4 warps in 2x2, warp tile 64x64, BK=32, 2-stage
// cp.async, 2 CTAs/SM. B rows interleave W1/W3 in 32-row groups so silu
// pairing is warp-local (acc[mi][ni] = W1, acc[mi][ni+4] = W3, same H col).
// ---------------------------------------------------------------------------
__global__ void __launch_bounds__(128, 2) k_gemm1(const float* __restrict__ x,
                                                  const float* __restrict__ W1,
                                                  const float* __restrict__ W3) {
    int e = blockIdx.z;
    int cnt = g_count[e];
    int m0 = blockIdx.x * 128;
    if (m0 >= cnt) return;
    int n0 = blockIdx.y * 64;   // 64 H-columns per block

    extern __shared__ __align__(16) char smem[];
    int* srow = (int*)smem;
    float* stages = (float*)(smem + 512);
    uint32_t sb = smem_u32(smem);
    int tid = threadIdx.x, w = tid >> 5, lane = tid & 31, gr = lane >> 2, tg = lane & 3;
    int wm = w >> 1, wn = w & 1;

    srow[tid] = g_tokens[e * CAP + m0 + tid] * DD;
    __syncthreads();

    const float* w1b = W1 + ((size_t)e * HH + n0) * DD;
    const float* w3b = W3 + ((size_t)e * HH + n0) * DD;

    auto issue = [&](int s) {
        if (s < NS1) {
            int k0 = s * BK;
            uint32_t bs = sb + 512 + (s & 1) * STAGE_B;
#pragma unroll
            for (int i = 0; i < 8; i++) {
                int u = tid + i * 128, row = u >> 3, c4 = u & 7;
                CP16(bs + (row * AST + c4 * 4) * 4, x + srow[row] + k0 + c4 * 4);
            }
#pragma unroll
            for (int i = 0; i < 8; i++) {
                int u = tid + i * 128, row = u >> 3, c4 = u & 7;
                int colh = (row >> 6) * 32 + (row & 31);
                const float* src = ((row & 32) ? w3b : w1b) + (size_t)colh * DD;
                CP16(bs + (OFF_B_W + row * AST + c4 * 4) * 4, src + k0 + c4 * 4);
            }
        }
        CP_COMMIT();
    };

    float acc[4][8][4];
#pragma unroll
    for (int mi = 0; mi < 4; mi++)
#pragma unroll
        for (int ni = 0; ni < 8; ni++)
#pragma unroll
            for (int q = 0; q < 4; q++) acc[mi][ni][q] = 0.0f;

    issue(0);
    for (int s = 0; s < NS1; s++) {
        CP_WAIT0();
        __syncthreads();
        issue(s + 1);
        const float* st = stages + (s & 1) * STAGE_W;
        const float* sB = st + OFF_B_W;
#pragma unroll
        for (int ks = 0; ks < 32; ks += 8) {
            uint32_t a[4][4];
#pragma unroll
            for (int mi = 0; mi < 4; mi++) {
                int r0 = wm * 64 + mi * 16 + gr;
                a[mi][0] = *(const uint32_t*)&st[r0 * AST + ks + tg];
                a[mi][1] = *(const uint32_t*)&st[(r0 + 8) * AST + ks + tg];
                a[mi][2] = *(const uint32_t*)&st[r0 * AST + ks + tg + 4];
                a[mi][3] = *(const uint32_t*)&st[(r0 + 8) * AST + ks + tg + 4];
            }
#pragma unroll
            for (int ni = 0; ni < 8; ni++) {
                int n = wn * 64 + ni * 8 + gr;
                uint32_t b0 = *(const uint32_t*)&sB[n * AST + ks + tg];
                uint32_t b1 = *(const uint32_t*)&sB[n * AST + ks + tg + 4];
#pragma unroll
                for (int mi = 0; mi < 4; mi++)
                    mma_tf32(acc[mi][ni], a[mi], b0, b1);
            }
        }
    }

    // epilogue: silu pairing warp-local (ni = W1, ni+4 = W3, same H column);
    // pre-round G to tf32 RNA so gemm2's in-MMA truncation is exact.
#pragma unroll
    for (int mi = 0; mi < 4; mi++) {
        int r = m0 + wm * 64 + mi * 16 + gr;
        float* gp = g_G + ((size_t)e * CAP + r) * HH + n0 + wn * 32;
#pragma unroll
        for (int ni = 0; ni < 4; ni++) {
            int c = ni * 8 + tg * 2;
            float2 v0, v1;
            v0.x = f2tf_rna(silu_f(acc[mi][ni][0]) * acc[mi][ni + 4][0]);
            v0.y = f2tf_rna(silu_f(acc[mi][ni][1]) * acc[mi][ni + 4][1]);
            v1.x = f2tf_rna(silu_f(acc[mi][ni][2]) * acc[mi][ni + 4][2]);
            v1.y = f2tf_rna(silu_f(acc[mi][ni][3]) * acc[mi][ni + 4][3]);
            *(float2*)(gp + c) = v0;
            *(float2*)(gp + (size_t)8 * HH + c) = v1;
        }
    }
}

// ---------------------------------------------------------------------------
// gemm2: block 128M x 128N (d-cols), 4 warps 2x2, warp tile 64x64, K over H.
// Weighted atomic scatter-add into out (pre-initialized to residual x).
// ---------------------------------------------------------------------------
__global__ void __launch_bounds__(128, 2) k_gemm2(const float* __restrict__ W2,
                                                  float* __restrict__ out) {
    int e = blockIdx.z;
    int cnt = g_count[e];
    int m0 = blockIdx.x * 128;
    if (m0 >= cnt) return;
    int n0 = blockIdx.y * 128;

    extern __shared__ __align__(16) char smem[];
    float* stages = (float*)(smem + 512);
    uint32_t sb = smem_u32(smem);
    int tid = threadIdx.x, w = tid >> 5, lane = tid & 31, gr = lane >> 2, tg = lane & 3;
    int wm = w >> 1, wn = w & 1;

    const float* ab  = g_G + ((size_t)e * CAP + m0) * HH;
    const float* w2b = W2 + ((size_t)e * DD + n0) * HH;

    auto issue = [&](int s) {
        if (s < NS2) {
            int k0 = s * BK;
            uint32_t bs = sb + 512 + (s & 1) * STAGE_B;
#pragma unroll
            for (int i = 0; i < 8; i++) {
                int u = tid + i * 128, row = u >> 3, c4 = u & 7;
                CP16(bs + (row * AST + c4 * 4) * 4, ab + (size_t)row * HH + k0 + c4 * 4);
            }
#pragma unroll
            for (int i = 0; i < 8; i++) {
                int u = tid + i * 128, row = u >> 3, c4 = u & 7;
                CP16(bs + (OFF_B_W + row * AST + c4 * 4) * 4, w2b + (size_t)row * HH + k0 + c4 * 4);
            }
        }
        CP_COMMIT();
    };

    float acc[4][8][4];
#pragma unroll
    for (int mi = 0; mi < 4; mi++)
#pragma unroll
        for (int ni = 0; ni < 8; ni++)
#pragma unroll
            for (int q = 0; q < 4; q++) acc[mi][ni][q] = 0.0f;

    issue(0);
    for (int s = 0; s < NS2; s++) {
        CP_WAIT0();
        __syncthreads();
        issue(s + 1);
        const float* st = stages + (s & 1) * STAGE_W;
        const float* sB = st + OFF_B_W;
#pragma unroll
        for (int ks = 0; ks < 32; ks += 8) {
            uint32_t a[4][4];
#pragma unroll
            for (int mi = 0; mi < 4; mi++) {
                int r0 = wm * 64 + mi * 16 + gr;
                a[mi][0] = *(const uint32_t*)&st[r0 * AST + ks + tg];
                a[mi][1] = *(const uint32_t*)&st[(r0 + 8) * AST + ks + tg];
                a[mi][2] = *(const uint32_t*)&st[r0 * AST + ks + tg + 4];
                a[mi][3] = *(const uint32_t*)&st[(r0 + 8) * AST + ks + tg + 4];
            }
#pragma unroll
            for (int ni = 0; ni < 8; ni++) {
                int n = wn * 64 + ni * 8 + gr;
                uint32_t b0 = *(const uint32_t*)&sB[n * AST + ks + tg];
                uint32_t b1 = *(const uint32_t*)&sB[n * AST + ks + tg + 4];
#pragma unroll
                for (int mi = 0; mi < 4; mi++)
                    mma_tf32(acc[mi][ni], a[mi], b0, b1);
            }
        }
    }

    // epilogue: weighted scatter-add
#pragma unroll
    for (int mi = 0; mi < 4; mi++) {
        int rl = m0 + wm * 64 + mi * 16 + gr;
        int t0 = g_tokens[e * CAP + rl];
        float w0 = g_w[e * CAP + rl];
        int t1 = g_tokens[e * CAP + rl + 8];
        float w1 = g_w[e * CAP + rl + 8];
        float* o0 = out + (size_t)t0 * DD + n0 + wn * 64;
        float* o1 = out + (size_t)t1 * DD + n0 + wn * 64;
#pragma unroll
        for (int ni = 0; ni < 8; ni++) {
            int c = ni * 8 + tg * 2;
            atomicAdd(o0 + c,     w0 * acc[mi][ni][0]);
            atomicAdd(o0 + c + 1, w0 * acc[mi][ni][1]);
            atomicAdd(o1 + c,     w1 * acc[mi][ni][2]);
            atomicAdd(o1 + c + 1, w1 * acc[mi][ni][3]);
        }
    }
}

// ---------------------------------------------------------------------------
extern "C" void kernel_launch(void* const* d_in, const int* in_sizes, int n_in,
                              void* d_out, int out_size) {
    (void)in_sizes; (void)n_in; (void)out_size;
    const float* x  = (const float*)d_in[0];
    const float* Wg = (const float*)d_in[1];
    const float* W1 = (const float*)d_in[2];
    const float* W3 = (const float*)d_in[3];
    const float* W2 = (const float*)d_in[4];
    float* out = (float*)d_out;

    cudaFuncSetAttribute(k_gemm1, cudaFuncAttributeMaxDynamicSharedMemorySize, SMEM_DYN);
    cudaFuncSetAttribute(k_gemm2, cudaFuncAttributeMaxDynamicSharedMemorySize, SMEM_DYN);

    k_init<<<(EE * CAP + 255) / 256, 256>>>();
    k_gate<<<TT / 8, 256>>>(x, Wg, out);
    k_route<<<TT / 256, 256>>>();
    dim3 g1(CAP / 128, HH / 64, EE);
    k_gemm1<<<g1, 128, SMEM_DYN>>>(x, W1, W3);
    dim3 g2(CAP / 128, DD / 128, EE);
    k_gemm2<<<g2, 128, SMEM_DYN>>>(W2, out);
}

// round 9
// speedup vs baseline: 1.7606x; 1.5938x over previous
#include <cuda_runtime.h>
#include <cuda_fp16.h>
#include <cstdint>

// Problem dims
#define DD 2048
#define HH 1408
#define EE 8
#define TT 4096
#define CAP 4096
#define WELEMS (EE * HH * DD)   // 23068672 per weight tensor

#define BK 64                    // halfs per stage
#define NS1 (DD / BK)            // 32
#define NS2 (HH / BK)            // 22
#define RSTRIDE 72               // SMEM row stride in halfs (144B) -> conflict-free frags
#define OFF_B_H (128 * RSTRIDE)  // B region offset (halfs) within stage
#define STAGE_B (256 * RSTRIDE * 2)       // 36864 bytes
#define SMEM_DYN (512 + 2 * STAGE_B)      // 74240 -> 2 CTAs/SM

// ---- global scratch (no allocs allowed) ----
__device__ int    g_count[EE];
__device__ int    g_tokens[EE * CAP];
__device__ float  g_w[EE * CAP];
__device__ int    g_tidx[TT * 2];
__device__ float  g_tw[TT * 2];
__device__ __half g_W1h[WELEMS];
__device__ __half g_W3h[WELEMS];
__device__ __half g_W2h[WELEMS];
__device__ __half g_xh[(size_t)TT * DD];
__device__ __half g_Gh[(size_t)EE * CAP * HH];

// ---------------------------------------------------------------------------
__device__ __forceinline__ uint32_t smem_u32(const void* p) {
    uint32_t a;
    asm("{ .reg .u64 t; cvta.to.shared.u64 t, %1; cvt.u32.u64 %0, t; }" : "=r"(a) : "l"(p));
    return a;
}
#define CP16(dst, src) \
    asm volatile("cp.async.cg.shared.global [%0], [%1], 16;" :: "r"(dst), "l"(src) : "memory")
#define CP_COMMIT() asm volatile("cp.async.commit_group;" ::: "memory")
#define CP_WAIT0()  asm volatile("cp.async.wait_group 0;" ::: "memory")

// fp16 m16n8k16, fp32 accumulate (fragment layout verified in R1 bf16 variant)
__device__ __forceinline__ void mma_f16(float* c, const uint32_t* a,
                                        uint32_t b0, uint32_t b1) {
    asm volatile(
        "mma.sync.aligned.m16n8k16.row.col.f32.f16.f16.f32 "
        "{%0,%1,%2,%3},{%4,%5,%6,%7},{%8,%9},{%0,%1,%2,%3};"
        : "+f"(c[0]), "+f"(c[1]), "+f"(c[2]), "+f"(c[3])
        : "r"(a[0]), "r"(a[1]), "r"(a[2]), "r"(a[3]), "r"(b0), "r"(b1));
}
__device__ __forceinline__ float silu_f(float v) { return v / (1.0f + expf(-v)); }

// ---------------------------------------------------------------------------
__global__ void k_init() {
    int i = blockIdx.x * blockDim.x + threadIdx.x;
    if (i < EE * CAP) { g_tokens[i] = 0; g_w[i] = 0.0f; }
    if (i < EE) g_count[i] = 0;
}

// streaming fp32 -> fp16 weight conversion (blockIdx.y selects tensor)
__global__ void __launch_bounds__(256) k_convert(const float* __restrict__ W1,
                                                 const float* __restrict__ W3,
                                                 const float* __restrict__ W2) {
    size_t i = ((size_t)blockIdx.x * blockDim.x + threadIdx.x) * 4;
    if (i >= WELEMS) return;
    const float* src;
    __half* dst;
    if (blockIdx.y == 0)      { src = W1; dst = g_W1h; }
    else if (blockIdx.y == 1) { src = W3; dst = g_W3h; }
    else                      { src = W2; dst = g_W2h; }
    float4 v = *(const float4*)(src + i);
    *(__half2*)(dst + i)     = __floats2half2_rn(v.x, v.y);
    *(__half2*)(dst + i + 2) = __floats2half2_rn(v.z, v.w);
}

// gating: one warp per token; writes out = x (residual) and x_h (fp16 copy).
__global__ void k_gate(const float* __restrict__ x,
                       const float* __restrict__ Wg,
                       float* __restrict__ out) {
    int warp = threadIdx.x >> 5, lane = threadIdx.x & 31;
    int t = blockIdx.x * 8 + warp;
    float a[EE];
#pragma unroll
    for (int e = 0; e < EE; e++) a[e] = 0.0f;
    const float4* xr = (const float4*)(x + (size_t)t * DD);
    const float4* wg = (const float4*)Wg;
    float4* orow = (float4*)(out + (size_t)t * DD);
    __half2* xh = (__half2*)(g_xh + (size_t)t * DD);
#pragma unroll 4
    for (int k = lane; k < DD / 4; k += 32) {
        float4 xv = xr[k];
        orow[k] = xv;
        xh[2 * k]     = __floats2half2_rn(xv.x, xv.y);
        xh[2 * k + 1] = __floats2half2_rn(xv.z, xv.w);
#pragma unroll
        for (int e = 0; e < EE; e++) {
            float4 wv = wg[e * (DD / 4) + k];
            a[e] += xv.x * wv.x + xv.y * wv.y + xv.z * wv.z + xv.w * wv.w;
        }
    }
#pragma unroll
    for (int off = 16; off; off >>= 1) {
#pragma unroll
        for (int e = 0; e < EE; e++) a[e] += __shfl_xor_sync(0xffffffffu, a[e], off);
    }
    if (lane == 0) {
        float m = a[0];
#pragma unroll
        for (int e = 1; e < EE; e++) m = fmaxf(m, a[e]);
        float s = 0.0f;
#pragma unroll
        for (int e = 0; e < EE; e++) s += expf(a[e] - m);
        int i1 = 0;
#pragma unroll
        for (int e = 1; e < EE; e++) if (a[e] > a[i1]) i1 = e;
        int i2 = (i1 == 0) ? 1 : 0;
#pragma unroll
        for (int e = 0; e < EE; e++) if (e != i1 && a[e] > a[i2]) i2 = e;
        g_tidx[t * 2 + 0] = i1; g_tw[t * 2 + 0] = expf(a[i1] - m) / s;
        g_tidx[t * 2 + 1] = i2; g_tw[t * 2 + 1] = expf(a[i2] - m) / s;
    }
}

__global__ void k_route() {
    int t = blockIdx.x * blockDim.x + threadIdx.x;
    if (t >= TT) return;
#pragma unroll
    for (int k = 0; k < 2; k++) {
        int e = g_tidx[t * 2 + k];
        int pos = atomicAdd(&g_count[e], 1);
        g_tokens[e * CAP + pos] = t;
        g_w[e * CAP + pos] = g_tw[t * 2 + k];
    }
}

// ---------------------------------------------------------------------------
// gemm1: block 128M x 128N fp16 HMMA.16816, 4 warps 2x2, warp tile 64x64,
// BK=64 halfs, 2-stage cp.async, 2 CTAs/SM. B rows interleave W1/W3 in
// 32-row groups -> silu pairing warp-local (acc[mi][ni] vs acc[mi][ni+4]).
// ---------------------------------------------------------------------------
__global__ void __launch_bounds__(128, 2) k_gemm1() {
    int e = blockIdx.z;
    int cnt = g_count[e];
    int m0 = blockIdx.x * 128;
    if (m0 >= cnt) return;
    int n0 = blockIdx.y * 64;   // 64 H-columns per block

    extern __shared__ __align__(16) char smem[];
    int* srow = (int*)smem;
    uint32_t sb = smem_u32(smem);
    int tid = threadIdx.x, w = tid >> 5, lane = tid & 31, gr = lane >> 2, tg = lane & 3;
    int wm = w >> 1, wn = w & 1;

    srow[tid] = g_tokens[e * CAP + m0 + tid] * DD;
    __syncthreads();

    const __half* w1b = g_W1h + ((size_t)e * HH + n0) * DD;
    const __half* w3b = g_W3h + ((size_t)e * HH + n0) * DD;

    auto issue = [&](int s) {
        if (s < NS1) {
            int k0 = s * BK;
            uint32_t bs = sb + 512 + (s & 1) * STAGE_B;
#pragma unroll
            for (int i = 0; i < 8; i++) {
                int u = tid + i * 128, row = u >> 3, c8 = u & 7;
                CP16(bs + row * 144 + c8 * 16, g_xh + srow[row] + k0 + c8 * 8);
            }
#pragma unroll
            for (int i = 0; i < 8; i++) {
                int u = tid + i * 128, row = u >> 3, c8 = u & 7;
                int colh = (row >> 6) * 32 + (row & 31);
                const __half* src = ((row & 32) ? w3b : w1b) + (size_t)colh * DD;
                CP16(bs + OFF_B_H * 2 + row * 144 + c8 * 16, src + k0 + c8 * 8);
            }
        }
        CP_COMMIT();
    };

    float acc[4][8][4];
#pragma unroll
    for (int mi = 0; mi < 4; mi++)
#pragma unroll
        for (int ni = 0; ni < 8; ni++)
#pragma unroll
            for (int q = 0; q < 4; q++) acc[mi][ni][q] = 0.0f;

    issue(0);
    for (int s = 0; s < NS1; s++) {
        CP_WAIT0();
        __syncthreads();
        issue(s + 1);
        const __half* st = (const __half*)(smem + 512 + (s & 1) * STAGE_B);
        const __half* sB = st + OFF_B_H;
#pragma unroll
        for (int ks = 0; ks < 64; ks += 16) {
            uint32_t a[4][4];
#pragma unroll
            for (int mi = 0; mi < 4; mi++) {
                int r0 = wm * 64 + mi * 16 + gr;
                a[mi][0] = *(const uint32_t*)&st[r0 * RSTRIDE + ks + tg * 2];
                a[mi][1] = *(const uint32_t*)&st[(r0 + 8) * RSTRIDE + ks + tg * 2];
                a[mi][2] = *(const uint32_t*)&st[r0 * RSTRIDE + ks + tg * 2 + 8];
                a[mi][3] = *(const uint32_t*)&st[(r0 + 8) * RSTRIDE + ks + tg * 2 + 8];
            }
#pragma unroll
            for (int ni = 0; ni < 8; ni++) {
                int n = wn * 64 + ni * 8 + gr;
                uint32_t b0 = *(const uint32_t*)&sB[n * RSTRIDE + ks + tg * 2];
                uint32_t b1 = *(const uint32_t*)&sB[n * RSTRIDE + ks + tg * 2 + 8];
#pragma unroll
                for (int mi = 0; mi < 4; mi++)
                    mma_f16(acc[mi][ni], a[mi], b0, b1);
            }
        }
    }

    // epilogue: silu pairing warp-local; store G as fp16
#pragma unroll
    for (int mi = 0; mi < 4; mi++) {
        int r = m0 + wm * 64 + mi * 16 + gr;
        __half* gp = g_Gh + ((size_t)e * CAP + r) * HH + n0 + wn * 32;
#pragma unroll
        for (int ni = 0; ni < 4; ni++) {
            int c = ni * 8 + tg * 2;
            float g0 = silu_f(acc[mi][ni][0]) * acc[mi][ni + 4][0];
            float g1 = silu_f(acc[mi][ni][1]) * acc[mi][ni + 4][1];
            float g2 = silu_f(acc[mi][ni][2]) * acc[mi][ni + 4][2];
            float g3 = silu_f(acc[mi][ni][3]) * acc[mi][ni + 4][3];
            *(__half2*)(gp + c) = __floats2half2_rn(g0, g1);
            *(__half2*)(gp + (size_t)8 * HH + c) = __floats2half2_rn(g2, g3);
        }
    }
}

// ---------------------------------------------------------------------------
// gemm2: block 128M x 128N (d-cols), fp16 HMMA, K over H; weighted atomic
// scatter-add into out (pre-initialized to residual x).
// ---------------------------------------------------------------------------
__global__ void __launch_bounds__(128, 2) k_gemm2(float* __restrict__ out) {
    int e = blockIdx.z;
    int cnt = g_count[e];
    int m0 = blockIdx.x * 128;
    if (m0 >= cnt) return;
    int n0 = blockIdx.y * 128;

    extern __shared__ __align__(16) char smem[];
    uint32_t sb = smem_u32(smem);
    int tid = threadIdx.x, w = tid >> 5, lane = tid & 31, gr = lane >> 2, tg = lane & 3;
    int wm = w >> 1, wn = w & 1;

    const __half* ab  = g_Gh + ((size_t)e * CAP + m0) * HH;
    const __half* w2b = g_W2h + ((size_t)e * DD + n0) * HH;

    auto issue = [&](int s) {
        if (s < NS2) {
            int k0 = s * BK;
            uint32_t bs = sb + 512 + (s & 1) * STAGE_B;
#pragma unroll
            for (int i = 0; i < 8; i++) {
                int u = tid + i * 128, row = u >> 3, c8 = u & 7;
                CP16(bs + row * 144 + c8 * 16, ab + (size_t)row * HH + k0 + c8 * 8);
            }
#pragma unroll
            for (int i = 0; i < 8; i++) {
                int u = tid + i * 128, row = u >> 3, c8 = u & 7;
                CP16(bs + OFF_B_H * 2 + row * 144 + c8 * 16,
                     w2b + (size_t)row * HH + k0 + c8 * 8);
            }
        }
        CP_COMMIT();
    };

    float acc[4][8][4];
#pragma unroll
    for (int mi = 0; mi < 4; mi++)
#pragma unroll
        for (int ni = 0; ni < 8; ni++)
#pragma unroll
            for (int q = 0; q < 4; q++) acc[mi][ni][q] = 0.0f;

    issue(0);
    for (int s = 0; s < NS2; s++) {
        CP_WAIT0();
        __syncthreads();
        issue(s + 1);
        const __half* st = (const __half*)(smem + 512 + (s & 1) * STAGE_B);
        const __half* sB = st + OFF_B_H;
#pragma unroll
        for (int ks = 0; ks < 64; ks += 16) {
            uint32_t a[4][4];
#pragma unroll
            for (int mi = 0; mi < 4; mi++) {
                int r0 = wm * 64 + mi * 16 + gr;
                a[mi][0] = *(const uint32_t*)&st[r0 * RSTRIDE + ks + tg * 2];
                a[mi][1] = *(const uint32_t*)&st[(r0 + 8) * RSTRIDE + ks + tg * 2];
                a[mi][2] = *(const uint32_t*)&st[r0 * RSTRIDE + ks + tg * 2 + 8];
                a[mi][3] = *(const uint32_t*)&st[(r0 + 8) * RSTRIDE + ks + tg * 2 + 8];
            }
#pragma unroll
            for (int ni = 0; ni < 8; ni++) {
                int n = wn * 64 + ni * 8 + gr;
                uint32_t b0 = *(const uint32_t*)&sB[n * RSTRIDE + ks + tg * 2];
                uint32_t b1 = *(const uint32_t*)&sB[n * RSTRIDE + ks + tg * 2 + 8];
#pragma unroll
                for (int mi = 0; mi < 4; mi++)
                    mma_f16(acc[mi][ni], a[mi], b0, b1);
            }
        }
    }

    // epilogue: weighted scatter-add
#pragma unroll
    for (int mi = 0; mi < 4; mi++) {
        int rl = m0 + wm * 64 + mi * 16 + gr;
        int t0 = g_tokens[e * CAP + rl];
        float w0 = g_w[e * CAP + rl];
        int t1 = g_tokens[e * CAP + rl + 8];
        float w1 = g_w[e * CAP + rl + 8];
        float* o0 = out + (size_t)t0 * DD + n0 + wn * 64;
        float* o1 = out + (size_t)t1 * DD + n0 + wn * 64;
#pragma unroll
        for (int ni = 0; ni < 8; ni++) {
            int c = ni * 8 + tg * 2;
            atomicAdd(o0 + c,     w0 * acc[mi][ni][0]);
            atomicAdd(o0 + c + 1, w0 * acc[mi][ni][1]);
            atomicAdd(o1 + c,     w1 * acc[mi][ni][2]);
            atomicAdd(o1 + c + 1, w1 * acc[mi][ni][3]);
        }
    }
}

// ---------------------------------------------------------------------------
extern "C" void kernel_launch(void* const* d_in, const int* in_sizes, int n_in,
                              void* d_out, int out_size) {
    (void)in_sizes; (void)n_in; (void)out_size;
    const float* x  = (const float*)d_in[0];
    const float* Wg = (const float*)d_in[1];
    const float* W1 = (const float*)d_in[2];
    const float* W3 = (const float*)d_in[3];
    const float* W2 = (const float*)d_in[4];
    float* out = (float*)d_out;

    cudaFuncSetAttribute(k_gemm1, cudaFuncAttributeMaxDynamicSharedMemorySize, SMEM_DYN);
    cudaFuncSetAttribute(k_gemm2, cudaFuncAttributeMaxDynamicSharedMemorySize, SMEM_DYN);

    k_convert<<<dim3((WELEMS / 4 + 255) / 256, 3), 256>>>(W1, W3, W2);
    k_init<<<(EE * CAP + 255) / 256, 256>>>();
    k_gate<<<TT / 8, 256>>>(x, Wg, out);
    k_route<<<TT / 256, 256>>>();
    dim3 g1(CAP / 128, HH / 64, EE);
    k_gemm1<<<g1, 128, SMEM_DYN>>>();
    dim3 g2(CAP / 128, DD / 128, EE);
    k_gemm2<<<g2, 128, SMEM_DYN>>>(out);
}

// round 10
// speedup vs baseline: 1.9262x; 1.0941x over previous
#include <cuda_runtime.h>
#include <cuda_fp16.h>
#include <cstdint>

// Problem dims
#define DD 2048
#define HH 1408
#define EE 8
#define TT 4096
#define CAP 4096
#define WELEMS (EE * HH * DD)

#define BK 64                     // halfs per stage (128B rows)
#define NS1 (DD / BK)             // 32
#define NS2 (HH / BK)             // 22
#define STAGE_B 32768             // 256 rows x 128 bytes
#define OFF_B 16384               // B region byte offset within stage
#define SMEM_DYN (512 + 3 * STAGE_B)   // 98816 -> 2 CTAs/SM

// ---- global scratch (no allocs allowed) ----
__device__ int    g_count[EE];
__device__ int    g_tokens[EE * CAP];
__device__ float  g_w[EE * CAP];
__device__ int    g_tidx[TT * 2];
__device__ float  g_tw[TT * 2];
__device__ __half g_W1h[WELEMS];
__device__ __half g_W3h[WELEMS];
__device__ __half g_W2h[WELEMS];
__device__ __half g_xh[(size_t)TT * DD];
__device__ __half g_Gh[(size_t)EE * CAP * HH];

// ---------------------------------------------------------------------------
__device__ __forceinline__ uint32_t smem_u32(const void* p) {
    uint32_t a;
    asm("{ .reg .u64 t; cvta.to.shared.u64 t, %1; cvt.u32.u64 %0, t; }" : "=r"(a) : "l"(p));
    return a;
}
#define CP16(dst, src) \
    asm volatile("cp.async.cg.shared.global [%0], [%1], 16;" :: "r"(dst), "l"(src) : "memory")
#define CP_COMMIT() asm volatile("cp.async.commit_group;" ::: "memory")
#define CP_WAIT1()  asm volatile("cp.async.wait_group 1;" ::: "memory")

// XOR-swizzled byte offset within a 128B-row tile region
__device__ __forceinline__ uint32_t swadr(int row, int chunk, int tg) {
    return (uint32_t)(row * 128 + ((chunk ^ (row & 7)) << 4) + tg * 4);
}

__device__ __forceinline__ void mma_f16(float* c, const uint32_t* a,
                                        uint32_t b0, uint32_t b1) {
    asm volatile(
        "mma.sync.aligned.m16n8k16.row.col.f32.f16.f16.f32 "
        "{%0,%1,%2,%3},{%4,%5,%6,%7},{%8,%9},{%0,%1,%2,%3};"
        : "+f"(c[0]), "+f"(c[1]), "+f"(c[2]), "+f"(c[3])
        : "r"(a[0]), "r"(a[1]), "r"(a[2]), "r"(a[3]), "r"(b0), "r"(b1));
}
__device__ __forceinline__ float silu_f(float v) { return v / (1.0f + expf(-v)); }

// ---------------------------------------------------------------------------
__global__ void k_init() {
    int i = blockIdx.x * blockDim.x + threadIdx.x;
    if (i < EE * CAP) { g_tokens[i] = 0; g_w[i] = 0.0f; }
    if (i < EE) g_count[i] = 0;
}

// streaming fp32 -> fp16 weight conversion (blockIdx.y selects tensor)
__global__ void __launch_bounds__(256) k_convert(const float* __restrict__ W1,
                                                 const float* __restrict__ W3,
                                                 const float* __restrict__ W2) {
    size_t i = ((size_t)blockIdx.x * blockDim.x + threadIdx.x) * 4;
    if (i >= WELEMS) return;
    const float* src;
    __half* dst;
    if (blockIdx.y == 0)      { src = W1; dst = g_W1h; }
    else if (blockIdx.y == 1) { src = W3; dst = g_W3h; }
    else                      { src = W2; dst = g_W2h; }
    float4 v = *(const float4*)(src + i);
    *(__half2*)(dst + i)     = __floats2half2_rn(v.x, v.y);
    *(__half2*)(dst + i + 2) = __floats2half2_rn(v.z, v.w);
}

// gating: one warp per token; writes out = x (residual) and x_h (fp16 copy).
__global__ void k_gate(const float* __restrict__ x,
                       const float* __restrict__ Wg,
                       float* __restrict__ out) {
    int warp = threadIdx.x >> 5, lane = threadIdx.x & 31;
    int t = blockIdx.x * 8 + warp;
    float a[EE];
#pragma unroll
    for (int e = 0; e < EE; e++) a[e] = 0.0f;
    const float4* xr = (const float4*)(x + (size_t)t * DD);
    const float4* wg = (const float4*)Wg;
    float4* orow = (float4*)(out + (size_t)t * DD);
    __half2* xh = (__half2*)(g_xh + (size_t)t * DD);
#pragma unroll 4
    for (int k = lane; k < DD / 4; k += 32) {
        float4 xv = xr[k];
        orow[k] = xv;
        xh[2 * k]     = __floats2half2_rn(xv.x, xv.y);
        xh[2 * k + 1] = __floats2half2_rn(xv.z, xv.w);
#pragma unroll
        for (int e = 0; e < EE; e++) {
            float4 wv = wg[e * (DD / 4) + k];
            a[e] += xv.x * wv.x + xv.y * wv.y + xv.z * wv.z + xv.w * wv.w;
        }
    }
#pragma unroll
    for (int off = 16; off; off >>= 1) {
#pragma unroll
        for (int e = 0; e < EE; e++) a[e] += __shfl_xor_sync(0xffffffffu, a[e], off);
    }
    if (lane == 0) {
        float m = a[0];
#pragma unroll
        for (int e = 1; e < EE; e++) m = fmaxf(m, a[e]);
        float s = 0.0f;
#pragma unroll
        for (int e = 0; e < EE; e++) s += expf(a[e] - m);
        int i1 = 0;
#pragma unroll
        for (int e = 1; e < EE; e++) if (a[e] > a[i1]) i1 = e;
        int i2 = (i1 == 0) ? 1 : 0;
#pragma unroll
        for (int e = 0; e < EE; e++) if (e != i1 && a[e] > a[i2]) i2 = e;
        g_tidx[t * 2 + 0] = i1; g_tw[t * 2 + 0] = expf(a[i1] - m) / s;
        g_tidx[t * 2 + 1] = i2; g_tw[t * 2 + 1] = expf(a[i2] - m) / s;
    }
}

__global__ void k_route() {
    int t = blockIdx.x * blockDim.x + threadIdx.x;
    if (t >= TT) return;
#pragma unroll
    for (int k = 0; k < 2; k++) {
        int e = g_tidx[t * 2 + k];
        int pos = atomicAdd(&g_count[e], 1);
        g_tokens[e * CAP + pos] = t;
        g_w[e * CAP + pos] = g_tw[t * 2 + k];
    }
}

// ---------------------------------------------------------------------------
// gemm1: block 128M x 128N fp16 HMMA.16816, 4 warps 2x2, warp tile 64x64,
// BK=64, XOR-swizzled SMEM (128B rows), 3-stage cp.async (wait_group 1),
// 2 CTAs/SM. B rows interleave W1/W3 in 32-row groups -> silu warp-local.
// ---------------------------------------------------------------------------
__global__ void __launch_bounds__(128, 2) k_gemm1() {
    int e = blockIdx.z;
    int cnt = g_count[e];
    int m0 = blockIdx.x * 128;
    if (m0 >= cnt) return;
    int n0 = blockIdx.y * 64;   // 64 H-columns per block

    extern __shared__ __align__(16) char smem[];
    int* srow = (int*)smem;
    uint32_t sb = smem_u32(smem);
    int tid = threadIdx.x, w = tid >> 5, lane = tid & 31, gr = lane >> 2, tg = lane & 3;
    int wm = w >> 1, wn = w & 1;

    srow[tid] = g_tokens[e * CAP + m0 + tid] * DD;
    __syncthreads();

    const __half* w1b = g_W1h + ((size_t)e * HH + n0) * DD;
    const __half* w3b = g_W3h + ((size_t)e * HH + n0) * DD;

    auto issue = [&](int s) {
        if (s < NS1) {
            int k0 = s * BK;
            uint32_t bs = sb + 512 + (s % 3) * STAGE_B;
#pragma unroll
            for (int i = 0; i < 8; i++) {
                int u = tid + i * 128, row = u >> 3, c8 = u & 7;
                CP16(bs + swadr(row, c8, 0), g_xh + srow[row] + k0 + c8 * 8);
            }
#pragma unroll
            for (int i = 0; i < 8; i++) {
                int u = tid + i * 128, row = u >> 3, c8 = u & 7;
                int colh = (row >> 6) * 32 + (row & 31);
                const __half* src = ((row & 32) ? w3b : w1b) + (size_t)colh * DD;
                CP16(bs + OFF_B + swadr(row, c8, 0), src + k0 + c8 * 8);
            }
        }
        CP_COMMIT();
    };

    float acc[4][8][4];
#pragma unroll
    for (int mi = 0; mi < 4; mi++)
#pragma unroll
        for (int ni = 0; ni < 8; ni++)
#pragma unroll
            for (int q = 0; q < 4; q++) acc[mi][ni][q] = 0.0f;

    issue(0);
    issue(1);
    for (int s = 0; s < NS1; s++) {
        CP_WAIT1();
        __syncthreads();
        issue(s + 2);
        const char* st = smem + 512 + (s % 3) * STAGE_B;
        const char* sB = st + OFF_B;
#pragma unroll
        for (int ks = 0; ks < 64; ks += 16) {
            int ck = ks >> 3;
            uint32_t a[4][4];
#pragma unroll
            for (int mi = 0; mi < 4; mi++) {
                int r0 = wm * 64 + mi * 16 + gr;
                a[mi][0] = *(const uint32_t*)(st + swadr(r0, ck, tg));
                a[mi][1] = *(const uint32_t*)(st + swadr(r0 + 8, ck, tg));
                a[mi][2] = *(const uint32_t*)(st + swadr(r0, ck + 1, tg));
                a[mi][3] = *(const uint32_t*)(st + swadr(r0 + 8, ck + 1, tg));
            }
#pragma unroll
            for (int ni = 0; ni < 8; ni++) {
                int n = wn * 64 + ni * 8 + gr;
                uint32_t b0 = *(const uint32_t*)(sB + swadr(n, ck, tg));
                uint32_t b1 = *(const uint32_t*)(sB + swadr(n, ck + 1, tg));
#pragma unroll
                for (int mi = 0; mi < 4; mi++)
                    mma_f16(acc[mi][ni], a[mi], b0, b1);
            }
        }
    }

    // epilogue: silu pairing warp-local; store G as fp16
#pragma unroll
    for (int mi = 0; mi < 4; mi++) {
        int r = m0 + wm * 64 + mi * 16 + gr;
        __half* gp = g_Gh + ((size_t)e * CAP + r) * HH + n0 + wn * 32;
#pragma unroll
        for (int ni = 0; ni < 4; ni++) {
            int c = ni * 8 + tg * 2;
            float g0 = silu_f(acc[mi][ni][0]) * acc[mi][ni + 4][0];
            float g1 = silu_f(acc[mi][ni][1]) * acc[mi][ni + 4][1];
            float g2 = silu_f(acc[mi][ni][2]) * acc[mi][ni + 4][2];
            float g3 = silu_f(acc[mi][ni][3]) * acc[mi][ni + 4][3];
            *(__half2*)(gp + c) = __floats2half2_rn(g0, g1);
            *(__half2*)(gp + (size_t)8 * HH + c) = __floats2half2_rn(g2, g3);
        }
    }
}

// ---------------------------------------------------------------------------
// gemm2: block 128M x 128N (d-cols), fp16 HMMA, K over H, same pipeline;
// weighted atomic scatter-add into out (pre-initialized to residual x).
// ---------------------------------------------------------------------------
__global__ void __launch_bounds__(128, 2) k_gemm2(float* __restrict__ out) {
    int e = blockIdx.z;
    int cnt = g_count[e];
    int m0 = blockIdx.x * 128;
    if (m0 >= cnt) return;
    int n0 = blockIdx.y * 128;

    extern __shared__ __align__(16) char smem[];
    uint32_t sb = smem_u32(smem);
    int tid = threadIdx.x, w = tid >> 5, lane = tid & 31, gr = lane >> 2, tg = lane & 3;
    int wm = w >> 1, wn = w & 1;

    const __half* ab  = g_Gh + ((size_t)e * CAP + m0) * HH;
    const __half* w2b = g_W2h + ((size_t)e * DD + n0) * HH;

    auto issue = [&](int s) {
        if (s < NS2) {
            int k0 = s * BK;
            uint32_t bs = sb + 512 + (s % 3) * STAGE_B;
#pragma unroll
            for (int i = 0; i < 8; i++) {
                int u = tid + i * 128, row = u >> 3, c8 = u & 7;
                CP16(bs + swadr(row, c8, 0), ab + (size_t)row * HH + k0 + c8 * 8);
            }
#pragma unroll
            for (int i = 0; i < 8; i++) {
                int u = tid + i * 128, row = u >> 3, c8 = u & 7;
                CP16(bs + OFF_B + swadr(row, c8, 0), w2b + (size_t)row * HH + k0 + c8 * 8);
            }
        }
        CP_COMMIT();
    };

    float acc[4][8][4];
#pragma unroll
    for (int mi = 0; mi < 4; mi++)
#pragma unroll
        for (int ni = 0; ni < 8; ni++)
#pragma unroll
            for (int q = 0; q < 4; q++) acc[mi][ni][q] = 0.0f;

    issue(0);
    issue(1);
    for (int s = 0; s < NS2; s++) {
        CP_WAIT1();
        __syncthreads();
        issue(s + 2);
        const char* st = smem + 512 + (s % 3) * STAGE_B;
        const char* sB = st + OFF_B;
#pragma unroll
        for (int ks = 0; ks < 64; ks += 16) {
            int ck = ks >> 3;
            uint32_t a[4][4];
#pragma unroll
            for (int mi = 0; mi < 4; mi++) {
                int r0 = wm * 64 + mi * 16 + gr;
                a[mi][0] = *(const uint32_t*)(st + swadr(r0, ck, tg));
                a[mi][1] = *(const uint32_t*)(st + swadr(r0 + 8, ck, tg));
                a[mi][2] = *(const uint32_t*)(st + swadr(r0, ck + 1, tg));
                a[mi][3] = *(const uint32_t*)(st + swadr(r0 + 8, ck + 1, tg));
            }
#pragma unroll
            for (int ni = 0; ni < 8; ni++) {
                int n = wn * 64 + ni * 8 + gr;
                uint32_t b0 = *(const uint32_t*)(sB + swadr(n, ck, tg));
                uint32_t b1 = *(const uint32_t*)(sB + swadr(n, ck + 1, tg));
#pragma unroll
                for (int mi = 0; mi < 4; mi++)
                    mma_f16(acc[mi][ni], a[mi], b0, b1);
            }
        }
    }

    // epilogue: weighted scatter-add
#pragma unroll
    for (int mi = 0; mi < 4; mi++) {
        int rl = m0 + wm * 64 + mi * 16 + gr;
        int t0 = g_tokens[e * CAP + rl];
        float w0 = g_w[e * CAP + rl];
        int t1 = g_tokens[e * CAP + rl + 8];
        float w1 = g_w[e * CAP + rl + 8];
        float* o0 = out + (size_t)t0 * DD + n0 + wn * 64;
        float* o1 = out + (size_t)t1 * DD + n0 + wn * 64;
#pragma unroll
        for (int ni = 0; ni < 8; ni++) {
            int c = ni * 8 + tg * 2;
            atomicAdd(o0 + c,     w0 * acc[mi][ni][0]);
            atomicAdd(o0 + c + 1, w0 * acc[mi][ni][1]);
            atomicAdd(o1 + c,     w1 * acc[mi][ni][2]);
            atomicAdd(o1 + c + 1, w1 * acc[mi][ni][3]);
        }
    }
}

// ---------------------------------------------------------------------------
extern "C" void kernel_launch(void* const* d_in, const int* in_sizes, int n_in,
                              void* d_out, int out_size) {
    (void)in_sizes; (void)n_in; (void)out_size;
    const float* x  = (const float*)d_in[0];
    const float* Wg = (const float*)d_in[1];
    const float* W1 = (const float*)d_in[2];
    const float* W3 = (const float*)d_in[3];
    const float* W2 = (const float*)d_in[4];
    float* out = (float*)d_out;

    cudaFuncSetAttribute(k_gemm1, cudaFuncAttributeMaxDynamicSharedMemorySize, SMEM_DYN);
    cudaFuncSetAttribute(k_gemm2, cudaFuncAttributeMaxDynamicSharedMemorySize, SMEM_DYN);

    k_convert<<<dim3((WELEMS / 4 + 255) / 256, 3), 256>>>(W1, W3, W2);
    k_init<<<(EE * CAP + 255) / 256, 256>>>();
    k_gate<<<TT / 8, 256>>>(x, Wg, out);
    k_route<<<TT / 256, 256>>>();
    dim3 g1(CAP / 128, HH / 64, EE);
    k_gemm1<<<g1, 128, SMEM_DYN>>>();
    dim3 g2(CAP / 128, DD / 128, EE);
    k_gemm2<<<g2, 128, SMEM_DYN>>>(out);
}